// round 1
// baseline (speedup 1.0000x reference)
#include <cuda_runtime.h>
#include <math.h>

#define Bsz 32
#define Tn  128
#define Nn  47
#define CIN 192
#define COUT 256
#define KK  3

// ---------------- scratch (device globals; no allocation at runtime) ----------------
__device__ float g_rowsum[KK * Nn];                          // 141
__device__ float g_wfull[(size_t)Nn * CIN * 512];            // 18.5 MB  [n][c][j], j<256 -> W_eff, j>=256 -> W_res
__device__ float g_hpre[(size_t)Bsz * Nn * COUT * Tn];       // 197 MB   [b][n][o][t]
__device__ float g_res [(size_t)Bsz * Nn * Tn * COUT];       // 197 MB   [b][n][t][o]

// ---------------- K0: row sums of normalized adjacency ----------------
__global__ void k_rowsum(const float* __restrict__ A, const float* __restrict__ adj) {
    int idx = threadIdx.x;
    if (idx < KK * Nn) {
        int k = idx / Nn, n = idx % Nn;
        const float* ar = A   + ((size_t)k * Nn + n) * Nn;
        const float* rr = adj + ((size_t)k * Nn + n) * Nn;
        float s = 0.f, sa = 0.f;
        for (int m = 0; m < Nn; m++) {
            float v = ar[m] + 0.3f * tanhf(rr[m]);
            s += v; sa += fabsf(v);
        }
        g_rowsum[idx] = s / fmaxf(sa, 1.0f);
    }
}

// ---------------- K1: fused per-node weight build ----------------
__global__ void k_wfull(const float* __restrict__ dw, const float* __restrict__ Wpw,
                        const float* __restrict__ Wres) {
    int idx = blockIdx.x * blockDim.x + threadIdx.x;
    if (idx >= Nn * CIN * 512) return;
    int j   = idx & 511;
    int rem = idx >> 9;          // n*CIN + c
    int c   = rem % CIN;
    int n   = rem / CIN;
    float w;
    if (j < COUT) {
        int o = j;
        w = 0.f;
#pragma unroll
        for (int k = 0; k < KK; k++)
            w += g_rowsum[k * Nn + n] * dw[k * CIN + c] * Wpw[(size_t)o * (KK * CIN) + k * CIN + c];
    } else {
        int o = j - COUT;
        w = Wres[(size_t)o * CIN + c];
    }
    g_wfull[idx] = w;
}

// ---------------- K2: per-node GEMM  (M=4096, K=192, N=512) ----------------
// block tile 64x128, BK=16, thread tile 4x8, 256 threads
__global__ void __launch_bounds__(256) k_gemm(const float* __restrict__ x) {
    const int nt = blockIdx.x;   // 0..3   (128-wide column tiles of the 512 outputs)
    const int mt = blockIdx.y;   // 0..63  (64-row tiles of M=4096)
    const int n  = blockIdx.z;   // 0..46

    __shared__ float As[16][68];   // [k][m] (padded)
    __shared__ float Bs[16][128];  // [k][j]

    const int tid  = threadIdx.x;
    const int row0 = (tid / 16) * 4;   // 0..60
    const int col0 = (tid % 16) * 8;   // 0..120

    float acc[4][8];
#pragma unroll
    for (int i = 0; i < 4; i++)
#pragma unroll
        for (int j = 0; j < 8; j++) acc[i][j] = 0.f;

    const int m0 = mt * 64;
    const int j0 = nt * 128;
    const float* wbase = g_wfull + ((size_t)n * CIN) * 512 + j0;

    const int ar = tid >> 2;          // 0..63
    const int ac = (tid & 3) * 4;     // 0..12
    const int bk = tid >> 4;          // 0..15
    const int bj = (tid & 15) * 8;    // 0..120

    for (int c0 = 0; c0 < CIN; c0 += 16) {
        // load A tile (x rows), transpose into As[k][m]
        float4 av = *(const float4*)&x[((size_t)(m0 + ar) * Nn + n) * CIN + c0 + ac];
        As[ac + 0][ar] = av.x; As[ac + 1][ar] = av.y;
        As[ac + 2][ar] = av.z; As[ac + 3][ar] = av.w;
        // load B tile
        const float* bp = wbase + (size_t)(c0 + bk) * 512 + bj;
        *(float4*)&Bs[bk][bj]     = *(const float4*)bp;
        *(float4*)&Bs[bk][bj + 4] = *(const float4*)(bp + 4);
        __syncthreads();

#pragma unroll
        for (int k = 0; k < 16; k++) {
            float4 a  = *(const float4*)&As[k][row0];
            float4 b0 = *(const float4*)&Bs[k][col0];
            float4 b1 = *(const float4*)&Bs[k][col0 + 4];
            float aa[4] = {a.x, a.y, a.z, a.w};
            float bb[8] = {b0.x, b0.y, b0.z, b0.w, b1.x, b1.y, b1.z, b1.w};
#pragma unroll
            for (int i = 0; i < 4; i++)
#pragma unroll
                for (int jj = 0; jj < 8; jj++) acc[i][jj] += aa[i] * bb[jj];
        }
        __syncthreads();
    }

    // epilogue: cols <256 -> h_pre [b][n][o][t], cols >=256 -> residual [b][n][t][o]
#pragma unroll
    for (int i = 0; i < 4; i++) {
        int m = m0 + row0 + i;
        int b = m >> 7;       // T = 128
        int t = m & 127;
#pragma unroll
        for (int jj = 0; jj < 8; jj++) {
            int j = j0 + col0 + jj;
            if (j < COUT) {
                g_hpre[(((size_t)b * Nn + n) * COUT + j) * Tn + t] = acc[i][jj];
            } else {
                g_res[(((size_t)b * Nn + n) * Tn + t) * COUT + (j - COUT)] = acc[i][jj];
            }
        }
    }
}

// ---------------- K3: fused depthwise-conv + GroupNorm + LayerNorm(+res) + GELU ----------------
// one block per (b,n); 256 threads (thread == channel); smem hbuf[256][129]+chA+chB
__global__ void __launch_bounds__(256) k_post(const float* __restrict__ convw,
                                              const float* __restrict__ gng,
                                              const float* __restrict__ gnb,
                                              const float* __restrict__ lng,
                                              const float* __restrict__ lnb,
                                              float* __restrict__ out) {
    extern __shared__ float sm[];
    float* hbuf = sm;                 // [256][129]
    float* chA  = sm + 256 * 129;     // 256
    float* chB  = chA + 256;          // 256

    const int n = blockIdx.x;
    const int b = blockIdx.y;
    const int o = threadIdx.x;

    // phase 1: temporal depthwise conv (KT=3, pad 1) + per-group (== per-warp) stats
    const float* src = g_hpre + (((size_t)b * Nn + n) * COUT + o) * Tn;
    const float w0 = convw[o * 3 + 0], w1 = convw[o * 3 + 1], w2 = convw[o * 3 + 2];
    float prev = 0.f, cur = src[0];
    float s = 0.f, s2 = 0.f;
    float* hrow = hbuf + o * 129;
#pragma unroll 4
    for (int t = 0; t < Tn; t++) {
        float nxt = (t < Tn - 1) ? src[t + 1] : 0.f;
        float v = w0 * prev + w1 * cur + w2 * nxt;
        hrow[t] = v; s += v; s2 += v * v;
        prev = cur; cur = nxt;
    }
#pragma unroll
    for (int off = 16; off; off >>= 1) {
        s  += __shfl_xor_sync(0xFFFFFFFFu, s,  off);
        s2 += __shfl_xor_sync(0xFFFFFFFFu, s2, off);
    }
    const float inv = 1.f / (32.f * Tn);
    float mu   = s * inv;
    float var  = s2 * inv - mu * mu;
    float rstd = rsqrtf(var + 1e-5f);
    float ga = gng[o] * rstd;
    chA[o] = ga;
    chB[o] = gnb[o] - mu * ga;
    __syncthreads();

    // phase 2: per-t LayerNorm over 256 channels (+residual) + exact GELU
    const int warp = o >> 5, lane = o & 31;
    const float* resbase = g_res + (((size_t)b * Nn + n) * Tn) * COUT;
    for (int t = warp; t < Tn; t += 8) {
        float y[8]; float su = 0.f, sq = 0.f;
#pragma unroll
        for (int jj = 0; jj < 8; jj++) {
            int oc = lane + 32 * jj;
            float v = hbuf[oc * 129 + t] * chA[oc] + chB[oc] + resbase[(size_t)t * COUT + oc];
            y[jj] = v; su += v; sq += v * v;
        }
#pragma unroll
        for (int off = 16; off; off >>= 1) {
            su += __shfl_xor_sync(0xFFFFFFFFu, su, off);
            sq += __shfl_xor_sync(0xFFFFFFFFu, sq, off);
        }
        float m2 = su * (1.f / 256.f);
        float vr = sq * (1.f / 256.f) - m2 * m2;
        float rs = rsqrtf(vr + 1e-5f);
        float* obase = out + (((size_t)b * Tn + t) * Nn + n) * COUT;
#pragma unroll
        for (int jj = 0; jj < 8; jj++) {
            int oc = lane + 32 * jj;
            float v = (y[jj] - m2) * rs * lng[oc] + lnb[oc];
            obase[oc] = 0.5f * v * (1.f + erff(v * 0.70710678118654752f));
        }
    }
}

// ---------------- launch ----------------
extern "C" void kernel_launch(void* const* d_in, const int* in_sizes, int n_in,
                              void* d_out, int out_size) {
    const float* x     = (const float*)d_in[0];
    const float* A     = (const float*)d_in[1];
    const float* dw    = (const float*)d_in[2];
    const float* adj   = (const float*)d_in[3];
    const float* Wpw   = (const float*)d_in[4];
    const float* convw = (const float*)d_in[5];
    const float* gng   = (const float*)d_in[6];
    const float* gnb   = (const float*)d_in[7];
    const float* lng   = (const float*)d_in[8];
    const float* lnb   = (const float*)d_in[9];
    const float* Wres  = (const float*)d_in[10];
    float* out = (float*)d_out;

    const int SMEM_POST = (256 * 129 + 512) * (int)sizeof(float);  // 134144
    cudaFuncSetAttribute(k_post, cudaFuncAttributeMaxDynamicSharedMemorySize, SMEM_POST);

    k_rowsum<<<1, 256>>>(A, adj);
    int total1 = Nn * CIN * 512;
    k_wfull<<<(total1 + 255) / 256, 256>>>(dw, Wpw, Wres);
    k_gemm<<<dim3(4, 64, 47), 256>>>(x);
    k_post<<<dim3(Nn, Bsz), 256, SMEM_POST>>>(convw, gng, gnb, lng, lnb, out);
}

// round 3
// speedup vs baseline: 3.5713x; 3.5713x over previous
#include <cuda_runtime.h>
#include <cuda_fp16.h>
#include <cstdint>
#include <math.h>

#define Bsz 32
#define Tn  128
#define Nn  47
#define CIN 192
#define COUT 256
#define KK  3

#define XS_PITCH 200   // halves per t-row (192 + pad)
#define HB_PITCH 264   // floats per t-row (256 + pad)
#define BS_PITCH 40    // halves per col-row (32 k + pad)

#define XS_BYTES (128 * XS_PITCH * 2)                 // 51200
#define HB_BYTES (128 * HB_PITCH * 4)                 // 135168
#define BS_BYTES (2 * 256 * BS_PITCH * 2)             // 40960
#define SMEM_TOTAL (XS_BYTES + HB_BYTES + BS_BYTES)   // 227328

// ---------------- scratch ----------------
__device__ float g_rowsum[KK * Nn];
__device__ __align__(256) __half g_wh[(size_t)Nn * 512 * CIN];  // [n][j][c]

// ---------------- K0: normalized adjacency row sums ----------------
__global__ void k_rowsum(const float* __restrict__ A, const float* __restrict__ adj) {
    int idx = threadIdx.x;
    if (idx < KK * Nn) {
        int k = idx / Nn, n = idx % Nn;
        const float* ar = A   + ((size_t)k * Nn + n) * Nn;
        const float* rr = adj + ((size_t)k * Nn + n) * Nn;
        float s = 0.f, sa = 0.f;
        for (int m = 0; m < Nn; m++) {
            float v = ar[m] + 0.3f * tanhf(rr[m]);
            s += v; sa += fabsf(v);
        }
        g_rowsum[idx] = s / fmaxf(sa, 1.0f);
    }
}

// ---------------- K1: build fp16 fused weights, layout [n][j][c] ----------------
__global__ void k_wh(const float* __restrict__ dw, const float* __restrict__ Wpw,
                     const float* __restrict__ Wres) {
    int idx = blockIdx.x * blockDim.x + threadIdx.x;
    if (idx >= Nn * 512 * CIN) return;
    int c = idx % CIN;
    int j = (idx / CIN) & 511;
    int n = idx / (CIN * 512);
    float w;
    if (j < COUT) {
        w = 0.f;
#pragma unroll
        for (int k = 0; k < KK; k++)
            w += g_rowsum[k * Nn + n] * dw[k * CIN + c] * Wpw[(size_t)j * (KK * CIN) + k * CIN + c];
    } else {
        w = Wres[(size_t)(j - COUT) * CIN + c];
    }
    g_wh[idx] = __float2half_rn(w);
}

// ---------------- helpers ----------------
__device__ __forceinline__ void cp_async16(uint32_t dst, const void* src) {
    asm volatile("cp.async.cg.shared.global [%0], [%1], 16;\n" :: "r"(dst), "l"(src));
}
__device__ __forceinline__ void mma16816(float* d, const uint32_t* a, const uint32_t* b) {
    asm volatile(
        "mma.sync.aligned.m16n8k16.row.col.f32.f16.f16.f32 "
        "{%0,%1,%2,%3}, {%4,%5,%6,%7}, {%8,%9}, {%0,%1,%2,%3};\n"
        : "+f"(d[0]), "+f"(d[1]), "+f"(d[2]), "+f"(d[3])
        : "r"(a[0]), "r"(a[1]), "r"(a[2]), "r"(a[3]), "r"(b[0]), "r"(b[1]));
}

// ---------------- K2: fully fused per-(b,n) block ----------------
__global__ void __launch_bounds__(256, 1)
k_fused(const float* __restrict__ x, const float* __restrict__ convw,
        const float* __restrict__ gng, const float* __restrict__ gnb,
        const float* __restrict__ lng, const float* __restrict__ lnb,
        float* __restrict__ out) {
    extern __shared__ char sm[];
    __half* xs   = (__half*)sm;                        // [128][200] halves
    float*  hbuf = (float*)(sm + XS_BYTES);            // [128][264] floats
    __half* bs   = (__half*)(sm + XS_BYTES + HB_BYTES); // 2 x [256][40] halves

    const int n = blockIdx.x, b = blockIdx.y;
    const int tid  = threadIdx.x;
    const int lane = tid & 31, warp = tid >> 5;
    const int g = lane >> 2, q = lane & 3;
    const int wm = warp & 1, wn = warp >> 1;

    const __half* wbase = g_wh + (size_t)n * 512 * CIN;

    // stage one 32-k chunk of B (256 cols) into buffer `buf` via cp.async
    auto stage = [&](int p, int kc, int buf) {
        const __half* src = wbase + (size_t)(p * 256 + tid) * CIN + kc * 32;
        uint32_t d = (uint32_t)__cvta_generic_to_shared(bs + buf * (256 * BS_PITCH) + tid * BS_PITCH);
        cp_async16(d,      src);
        cp_async16(d + 16, src + 8);
        cp_async16(d + 32, src + 16);
        cp_async16(d + 48, src + 24);
        asm volatile("cp.async.commit_group;\n");
    };

    // ---- load x tile -> fp16 smem (overlap with first B stage) ----
    stage(0, 0, 0);
    for (int i = tid; i < 128 * 48; i += 256) {
        int t = i / 48, c4 = (i % 48) * 4;
        float4 v = *(const float4*)(x + ((size_t)(b * Tn + t) * Nn + n) * CIN + c4);
        __half2* dst = (__half2*)(xs + t * XS_PITCH + c4);
        dst[0] = __floats2half2_rn(v.x, v.y);
        dst[1] = __floats2half2_rn(v.z, v.w);
    }
    __syncthreads();

    float acc[4][8][4];

#pragma unroll 1
    for (int p = 0; p < 2; p++) {
#pragma unroll
        for (int mi = 0; mi < 4; mi++)
#pragma unroll
            for (int ni = 0; ni < 8; ni++)
#pragma unroll
                for (int r = 0; r < 4; r++) acc[mi][ni][r] = 0.f;

        if (p == 1) stage(1, 0, 0);

#pragma unroll 1
        for (int kc = 0; kc < 6; kc++) {
            if (kc < 5) {
                stage(p, kc + 1, (kc + 1) & 1);
                asm volatile("cp.async.wait_group 1;\n");
            } else {
                asm volatile("cp.async.wait_group 0;\n");
            }
            __syncthreads();

            const __half* bsc = bs + (kc & 1) * (256 * BS_PITCH);
#pragma unroll
            for (int ks = 0; ks < 2; ks++) {
                const int kb = kc * 32 + ks * 16;
                uint32_t afr[4][4];
#pragma unroll
                for (int mi = 0; mi < 4; mi++) {
                    int t = wm * 64 + mi * 16 + g;
                    afr[mi][0] = *(const uint32_t*)(xs + t       * XS_PITCH + kb + 2 * q);
                    afr[mi][1] = *(const uint32_t*)(xs + (t + 8) * XS_PITCH + kb + 2 * q);
                    afr[mi][2] = *(const uint32_t*)(xs + t       * XS_PITCH + kb + 2 * q + 8);
                    afr[mi][3] = *(const uint32_t*)(xs + (t + 8) * XS_PITCH + kb + 2 * q + 8);
                }
#pragma unroll
                for (int ni = 0; ni < 8; ni++) {
                    int col = wn * 64 + ni * 8 + g;
                    uint32_t bfr[2];
                    bfr[0] = *(const uint32_t*)(bsc + col * BS_PITCH + ks * 16 + 2 * q);
                    bfr[1] = *(const uint32_t*)(bsc + col * BS_PITCH + ks * 16 + 2 * q + 8);
#pragma unroll
                    for (int mi = 0; mi < 4; mi++) mma16816(acc[mi][ni], afr[mi], bfr);
                }
            }
            __syncthreads();
        }

        if (p == 0) {
            // write h into hbuf[t][o]
#pragma unroll
            for (int mi = 0; mi < 4; mi++) {
                int t0 = wm * 64 + mi * 16 + g;
#pragma unroll
                for (int ni = 0; ni < 8; ni++) {
                    int o0 = wn * 64 + ni * 8 + 2 * q;
                    *(float2*)(hbuf + t0 * HB_PITCH + o0)       = make_float2(acc[mi][ni][0], acc[mi][ni][1]);
                    *(float2*)(hbuf + (t0 + 8) * HB_PITCH + o0) = make_float2(acc[mi][ni][2], acc[mi][ni][3]);
                }
            }
            __syncthreads();

            // ---- temporal depthwise conv + GroupNorm (group == warp) ----
            const int o = tid;
            const float w0 = convw[o * 3], w1 = convw[o * 3 + 1], w2 = convw[o * 3 + 2];
            float prev = 0.f, cur = hbuf[o];
            float s = 0.f, s2 = 0.f;
#pragma unroll 4
            for (int t = 0; t < Tn; t++) {
                float nxt = (t < Tn - 1) ? hbuf[(t + 1) * HB_PITCH + o] : 0.f;
                float v = w0 * prev + w1 * cur + w2 * nxt;
                hbuf[t * HB_PITCH + o] = v;
                s += v; s2 += v * v;
                prev = cur; cur = nxt;
            }
#pragma unroll
            for (int off = 16; off; off >>= 1) {
                s  += __shfl_xor_sync(0xFFFFFFFFu, s,  off);
                s2 += __shfl_xor_sync(0xFFFFFFFFu, s2, off);
            }
            const float inv = 1.f / (32.f * Tn);
            float mu = s * inv;
            float var = s2 * inv - mu * mu;
            float rstd = rsqrtf(var + 1e-5f);
            float ga = gng[o] * rstd;
            float gb = gnb[o] - mu * ga;
#pragma unroll 4
            for (int t = 0; t < Tn; t++)
                hbuf[t * HB_PITCH + o] = hbuf[t * HB_PITCH + o] * ga + gb;
            __syncthreads();
        } else {
            // accumulate residual: hbuf += res
#pragma unroll
            for (int mi = 0; mi < 4; mi++) {
                int t0 = wm * 64 + mi * 16 + g;
#pragma unroll
                for (int ni = 0; ni < 8; ni++) {
                    int o0 = wn * 64 + ni * 8 + 2 * q;
                    float2* p0 = (float2*)(hbuf + t0 * HB_PITCH + o0);
                    float2* p1 = (float2*)(hbuf + (t0 + 8) * HB_PITCH + o0);
                    float2 v0 = *p0, v1 = *p1;
                    v0.x += acc[mi][ni][0]; v0.y += acc[mi][ni][1];
                    v1.x += acc[mi][ni][2]; v1.y += acc[mi][ni][3];
                    *p0 = v0; *p1 = v1;
                }
            }
            __syncthreads();
        }
    }

    // ---- LayerNorm over 256 channels per t + exact GELU + store ----
    float lg[8], lb[8];
#pragma unroll
    for (int j = 0; j < 8; j++) { lg[j] = lng[lane + 32 * j]; lb[j] = lnb[lane + 32 * j]; }

    for (int t = warp; t < Tn; t += 8) {
        float y[8]; float su = 0.f, sq = 0.f;
#pragma unroll
        for (int j = 0; j < 8; j++) {
            float v = hbuf[t * HB_PITCH + lane + 32 * j];
            y[j] = v; su += v; sq += v * v;
        }
#pragma unroll
        for (int off = 16; off; off >>= 1) {
            su += __shfl_xor_sync(0xFFFFFFFFu, su, off);
            sq += __shfl_xor_sync(0xFFFFFFFFu, sq, off);
        }
        float mu = su * (1.f / 256.f);
        float var = sq * (1.f / 256.f) - mu * mu;
        float rs = rsqrtf(var + 1e-5f);
        float* ob = out + ((size_t)(b * Tn + t) * Nn + n) * COUT;
#pragma unroll
        for (int j = 0; j < 8; j++) {
            float v = (y[j] - mu) * rs * lg[j] + lb[j];
            ob[lane + 32 * j] = 0.5f * v * (1.f + erff(v * 0.70710678118654752f));
        }
    }
}

// ---------------- launch ----------------
extern "C" void kernel_launch(void* const* d_in, const int* in_sizes, int n_in,
                              void* d_out, int out_size) {
    const float* x     = (const float*)d_in[0];
    const float* A     = (const float*)d_in[1];
    const float* dw    = (const float*)d_in[2];
    const float* adj   = (const float*)d_in[3];
    const float* Wpw   = (const float*)d_in[4];
    const float* convw = (const float*)d_in[5];
    const float* gng   = (const float*)d_in[6];
    const float* gnb   = (const float*)d_in[7];
    const float* lng   = (const float*)d_in[8];
    const float* lnb   = (const float*)d_in[9];
    const float* Wres  = (const float*)d_in[10];
    float* out = (float*)d_out;

    cudaFuncSetAttribute(k_fused, cudaFuncAttributeMaxDynamicSharedMemorySize, SMEM_TOTAL);

    k_rowsum<<<1, 256>>>(A, adj);
    int total1 = Nn * 512 * CIN;
    k_wh<<<(total1 + 255) / 256, 256>>>(dw, Wpw, Wres);
    k_fused<<<dim3(Nn, Bsz), 256, SMEM_TOTAL>>>(x, convw, gng, gnb, lng, lnb, out);
}

// round 6
// speedup vs baseline: 5.1379x; 1.4387x over previous
#include <cuda_runtime.h>
#include <cuda_fp16.h>
#include <cstdint>
#include <math.h>

#define Bsz 32
#define Tn  128
#define Nn  47
#define CIN 192
#define COUT 256
#define KK  3

#define XS_PITCH 200   // halves per t-row (192 + pad)
#define HB_PITCH 264   // floats per t-row (256 + pad)
#define BS_PITCH 40    // halves per col-row (32 k + pad)

#define XS_BYTES (128 * XS_PITCH * 2)                 // 51200
#define HB_BYTES (128 * HB_PITCH * 4)                 // 135168
#define BS_BYTES (2 * 256 * BS_PITCH * 2)             // 40960
#define SMEM_TOTAL (XS_BYTES + HB_BYTES + BS_BYTES)   // 227328

// ---------------- scratch ----------------
__device__ __align__(256) __half g_wh[(size_t)Nn * 512 * CIN];  // [n][j][c]

// ---------------- K1: rowsum (in-block) + fused fp16 weights [n][j][c] ----------------
__global__ void __launch_bounds__(256) k_wh(const float* __restrict__ A, const float* __restrict__ adj,
                                            const float* __restrict__ dw, const float* __restrict__ Wpw,
                                            const float* __restrict__ Wres) {
    __shared__ float srs[KK][2];   // rowsum for (k, n0 + {0,1})
    const int idx0 = blockIdx.x * 256;
    const int n0 = idx0 / (512 * CIN);
    const int warp = threadIdx.x >> 5, lane = threadIdx.x & 31;
    if (warp < 6) {
        int k = warp % KK, nn = n0 + warp / KK;
        if (nn < Nn) {
            const float* ar = A   + ((size_t)k * Nn + nn) * Nn;
            const float* rr = adj + ((size_t)k * Nn + nn) * Nn;
            float s = 0.f, sa = 0.f;
            for (int m = lane; m < Nn; m += 32) {
                float v = ar[m] + 0.3f * tanhf(rr[m]);
                s += v; sa += fabsf(v);
            }
#pragma unroll
            for (int o = 16; o; o >>= 1) {
                s  += __shfl_xor_sync(0xFFFFFFFFu, s,  o);
                sa += __shfl_xor_sync(0xFFFFFFFFu, sa, o);
            }
            if (lane == 0) srs[k][warp / KK] = s / fmaxf(sa, 1.0f);
        }
    }
    __syncthreads();

    const int idx = idx0 + threadIdx.x;
    if (idx >= Nn * 512 * CIN) return;
    int c = idx % CIN;
    int j = (idx / CIN) & 511;
    int n = idx / (CIN * 512);
    float w;
    if (j < COUT) {
        w = 0.f;
#pragma unroll
        for (int k = 0; k < KK; k++)
            w += srs[k][n - n0] * dw[k * CIN + c] * Wpw[(size_t)j * (KK * CIN) + k * CIN + c];
    } else {
        w = Wres[(size_t)(j - COUT) * CIN + c];
    }
    g_wh[idx] = __float2half_rn(w);
}

// ---------------- helpers ----------------
__device__ __forceinline__ void cp_async16(uint32_t dst, const void* src) {
    asm volatile("cp.async.cg.shared.global [%0], [%1], 16;\n" :: "r"(dst), "l"(src));
}
__device__ __forceinline__ void mma16816(float* d, const uint32_t* a, const uint32_t* b) {
    asm volatile(
        "mma.sync.aligned.m16n8k16.row.col.f32.f16.f16.f32 "
        "{%0,%1,%2,%3}, {%4,%5,%6,%7}, {%8,%9}, {%0,%1,%2,%3};\n"
        : "+f"(d[0]), "+f"(d[1]), "+f"(d[2]), "+f"(d[3])
        : "r"(a[0]), "r"(a[1]), "r"(a[2]), "r"(a[3]), "r"(b[0]), "r"(b[1]));
}

// ---------------- K2: fully fused per-(b,n) block ----------------
__global__ void __launch_bounds__(256, 1)
k_fused(const float* __restrict__ x, const float* __restrict__ convw,
        const float* __restrict__ gng, const float* __restrict__ gnb,
        const float* __restrict__ lng, const float* __restrict__ lnb,
        float* __restrict__ out) {
    extern __shared__ char sm[];
    __half* xs   = (__half*)sm;                        // [128][200] halves
    float*  hbuf = (float*)(sm + XS_BYTES);            // [128][264] floats
    __half* bs   = (__half*)(sm + XS_BYTES + HB_BYTES); // 2 x [256][40] halves

    const int n = blockIdx.x, b = blockIdx.y;
    const int tid  = threadIdx.x;
    const int lane = tid & 31, warp = tid >> 5;
    const int g = lane >> 2, q = lane & 3;
    const int wm = warp & 1, wn = warp >> 1;

    const __half* wbase = g_wh + (size_t)n * 512 * CIN;

    // stage one 32-k chunk of B (256 cols) into buffer `buf` via cp.async
    auto stage = [&](int p, int kc, int buf) {
        const __half* src = wbase + (size_t)(p * 256 + tid) * CIN + kc * 32;
        uint32_t d = (uint32_t)__cvta_generic_to_shared(bs + buf * (256 * BS_PITCH) + tid * BS_PITCH);
        cp_async16(d,      src);
        cp_async16(d + 16, src + 8);
        cp_async16(d + 32, src + 16);
        cp_async16(d + 48, src + 24);
        asm volatile("cp.async.commit_group;\n");
    };

    // ---- load x tile -> fp16 smem (overlap with first B stage) ----
    stage(0, 0, 0);
    for (int i = tid; i < 128 * 48; i += 256) {
        int t = i / 48, c4 = (i % 48) * 4;
        float4 v = *(const float4*)(x + ((size_t)(b * Tn + t) * Nn + n) * CIN + c4);
        __half2* dst = (__half2*)(xs + t * XS_PITCH + c4);
        dst[0] = __floats2half2_rn(v.x, v.y);
        dst[1] = __floats2half2_rn(v.z, v.w);
    }
    __syncthreads();

    float acc[4][8][4];

#pragma unroll 1
    for (int p = 0; p < 2; p++) {
#pragma unroll
        for (int mi = 0; mi < 4; mi++)
#pragma unroll
            for (int ni = 0; ni < 8; ni++)
#pragma unroll
                for (int r = 0; r < 4; r++) acc[mi][ni][r] = 0.f;

        if (p == 1) stage(1, 0, 0);

#pragma unroll 1
        for (int kc = 0; kc < 6; kc++) {
            if (kc < 5) {
                stage(p, kc + 1, (kc + 1) & 1);
                asm volatile("cp.async.wait_group 1;\n");
            } else {
                asm volatile("cp.async.wait_group 0;\n");
            }
            __syncthreads();

            const __half* bsc = bs + (kc & 1) * (256 * BS_PITCH);
#pragma unroll
            for (int ks = 0; ks < 2; ks++) {
                const int kb = kc * 32 + ks * 16;
                uint32_t afr[4][4];
                uint32_t bfr[8][2];
#pragma unroll
                for (int mi = 0; mi < 4; mi++) {
                    int t = wm * 64 + mi * 16 + g;
                    afr[mi][0] = *(const uint32_t*)(xs + t       * XS_PITCH + kb + 2 * q);
                    afr[mi][1] = *(const uint32_t*)(xs + (t + 8) * XS_PITCH + kb + 2 * q);
                    afr[mi][2] = *(const uint32_t*)(xs + t       * XS_PITCH + kb + 2 * q + 8);
                    afr[mi][3] = *(const uint32_t*)(xs + (t + 8) * XS_PITCH + kb + 2 * q + 8);
                }
#pragma unroll
                for (int ni = 0; ni < 8; ni++) {
                    int col = wn * 64 + ni * 8 + g;
                    bfr[ni][0] = *(const uint32_t*)(bsc + col * BS_PITCH + ks * 16 + 2 * q);
                    bfr[ni][1] = *(const uint32_t*)(bsc + col * BS_PITCH + ks * 16 + 2 * q + 8);
                }
#pragma unroll
                for (int ni = 0; ni < 8; ni++)
#pragma unroll
                    for (int mi = 0; mi < 4; mi++)
                        mma16816(acc[mi][ni], afr[mi], bfr[ni]);
            }
            __syncthreads();
        }

        if (p == 0) {
            // write h into hbuf[t][o]
#pragma unroll
            for (int mi = 0; mi < 4; mi++) {
                int t0 = wm * 64 + mi * 16 + g;
#pragma unroll
                for (int ni = 0; ni < 8; ni++) {
                    int o0 = wn * 64 + ni * 8 + 2 * q;
                    *(float2*)(hbuf + t0 * HB_PITCH + o0)       = make_float2(acc[mi][ni][0], acc[mi][ni][1]);
                    *(float2*)(hbuf + (t0 + 8) * HB_PITCH + o0) = make_float2(acc[mi][ni][2], acc[mi][ni][3]);
                }
            }
            __syncthreads();

            // ---- temporal depthwise conv + GroupNorm (group == warp) ----
            const int o = tid;
            const float w0 = convw[o * 3], w1 = convw[o * 3 + 1], w2 = convw[o * 3 + 2];
            float prev = 0.f, cur = hbuf[o];
            float s = 0.f, s2 = 0.f;
#pragma unroll 4
            for (int t = 0; t < Tn; t++) {
                float nxt = (t < Tn - 1) ? hbuf[(t + 1) * HB_PITCH + o] : 0.f;
                float v = w0 * prev + w1 * cur + w2 * nxt;
                hbuf[t * HB_PITCH + o] = v;
                s += v; s2 += v * v;
                prev = cur; cur = nxt;
            }
#pragma unroll
            for (int off = 16; off; off >>= 1) {
                s  += __shfl_xor_sync(0xFFFFFFFFu, s,  off);
                s2 += __shfl_xor_sync(0xFFFFFFFFu, s2, off);
            }
            const float inv = 1.f / (32.f * Tn);
            float mu = s * inv;
            float var = s2 * inv - mu * mu;
            float rstd = rsqrtf(var + 1e-5f);
            float ga = gng[o] * rstd;
            float gb = gnb[o] - mu * ga;
#pragma unroll 4
            for (int t = 0; t < Tn; t++)
                hbuf[t * HB_PITCH + o] = hbuf[t * HB_PITCH + o] * ga + gb;
            __syncthreads();
        } else {
            // accumulate residual: hbuf += res
#pragma unroll
            for (int mi = 0; mi < 4; mi++) {
                int t0 = wm * 64 + mi * 16 + g;
#pragma unroll
                for (int ni = 0; ni < 8; ni++) {
                    int o0 = wn * 64 + ni * 8 + 2 * q;
                    float2* p0 = (float2*)(hbuf + t0 * HB_PITCH + o0);
                    float2* p1 = (float2*)(hbuf + (t0 + 8) * HB_PITCH + o0);
                    float2 v0 = *p0, v1 = *p1;
                    v0.x += acc[mi][ni][0]; v0.y += acc[mi][ni][1];
                    v1.x += acc[mi][ni][2]; v1.y += acc[mi][ni][3];
                    *p0 = v0; *p1 = v1;
                }
            }
            __syncthreads();
        }
    }

    // ---- LayerNorm over 256 channels per t + exact GELU + store ----
    float lg[8], lb[8];
#pragma unroll
    for (int j = 0; j < 8; j++) { lg[j] = lng[lane + 32 * j]; lb[j] = lnb[lane + 32 * j]; }

    for (int t = warp; t < Tn; t += 8) {
        float y[8]; float su = 0.f, sq = 0.f;
#pragma unroll
        for (int j = 0; j < 8; j++) {
            float v = hbuf[t * HB_PITCH + lane + 32 * j];
            y[j] = v; su += v; sq += v * v;
        }
#pragma unroll
        for (int off = 16; off; off >>= 1) {
            su += __shfl_xor_sync(0xFFFFFFFFu, su, off);
            sq += __shfl_xor_sync(0xFFFFFFFFu, sq, off);
        }
        float mu = su * (1.f / 256.f);
        float var = sq * (1.f / 256.f) - mu * mu;
        float rs = rsqrtf(var + 1e-5f);
        float* ob = out + ((size_t)(b * Tn + t) * Nn + n) * COUT;
#pragma unroll
        for (int j = 0; j < 8; j++) {
            float v = (y[j] - mu) * rs * lg[j] + lb[j];
            ob[lane + 32 * j] = 0.5f * v * (1.f + erff(v * 0.70710678118654752f));
        }
    }
}

// ---------------- launch ----------------
extern "C" void kernel_launch(void* const* d_in, const int* in_sizes, int n_in,
                              void* d_out, int out_size) {
    const float* x     = (const float*)d_in[0];
    const float* A     = (const float*)d_in[1];
    const float* dw    = (const float*)d_in[2];
    const float* adj   = (const float*)d_in[3];
    const float* Wpw   = (const float*)d_in[4];
    const float* convw = (const float*)d_in[5];
    const float* gng   = (const float*)d_in[6];
    const float* gnb   = (const float*)d_in[7];
    const float* lng   = (const float*)d_in[8];
    const float* lnb   = (const float*)d_in[9];
    const float* Wres  = (const float*)d_in[10];
    float* out = (float*)d_out;

    cudaFuncSetAttribute(k_fused, cudaFuncAttributeMaxDynamicSharedMemorySize, SMEM_TOTAL);

    int total1 = Nn * 512 * CIN;
    k_wh<<<(total1 + 255) / 256, 256>>>(A, adj, dw, Wpw, Wres);
    k_fused<<<dim3(Nn, Bsz), 256, SMEM_TOTAL>>>(x, convw, gng, gnb, lng, lnb, out);
}

// round 7
// speedup vs baseline: 5.1880x; 1.0098x over previous
#include <cuda_runtime.h>
#include <cuda_fp16.h>
#include <cstdint>
#include <math.h>

#define Bsz 32
#define Tn  128
#define Nn  47
#define CIN 192
#define COUT 256
#define KK  3

#define XS_PITCH 200   // halves per t-row (192 + pad)
#define HB_PITCH 264   // floats per t-row (256 + pad)
#define BS_PITCH 40    // halves per col-row (32 k + pad)

#define XS_BYTES (128 * XS_PITCH * 2)                 // 51200
#define HB_BYTES (128 * HB_PITCH * 4)                 // 135168
#define BS_BYTES (2 * 256 * BS_PITCH * 2)             // 40960
#define SMEM_TOTAL (XS_BYTES + HB_BYTES + BS_BYTES)   // 227328

// ---------------- scratch ----------------
__device__ __align__(256) __half g_wh[(size_t)Nn * 512 * CIN];  // [n][j][c]

// ---------------- K1: rowsum (in-block) + fused fp16 weights [n][j][c] ----------------
__global__ void __launch_bounds__(256) k_wh(const float* __restrict__ A, const float* __restrict__ adj,
                                            const float* __restrict__ dw, const float* __restrict__ Wpw,
                                            const float* __restrict__ Wres) {
    __shared__ float srs[KK][2];   // rowsum for (k, n0 + {0,1})
    const int idx0 = blockIdx.x * 256;
    const int n0 = idx0 / (512 * CIN);
    const int warp = threadIdx.x >> 5, lane = threadIdx.x & 31;
    if (warp < 6) {
        int k = warp % KK, nn = n0 + warp / KK;
        if (nn < Nn) {
            const float* ar = A   + ((size_t)k * Nn + nn) * Nn;
            const float* rr = adj + ((size_t)k * Nn + nn) * Nn;
            float s = 0.f, sa = 0.f;
            for (int m = lane; m < Nn; m += 32) {
                float v = ar[m] + 0.3f * tanhf(rr[m]);
                s += v; sa += fabsf(v);
            }
#pragma unroll
            for (int o = 16; o; o >>= 1) {
                s  += __shfl_xor_sync(0xFFFFFFFFu, s,  o);
                sa += __shfl_xor_sync(0xFFFFFFFFu, sa, o);
            }
            if (lane == 0) srs[k][warp / KK] = s / fmaxf(sa, 1.0f);
        }
    }
    __syncthreads();

    const int idx = idx0 + threadIdx.x;
    if (idx >= Nn * 512 * CIN) return;
    int c = idx % CIN;
    int j = (idx / CIN) & 511;
    int n = idx / (CIN * 512);
    float w;
    if (j < COUT) {
        w = 0.f;
#pragma unroll
        for (int k = 0; k < KK; k++)
            w += srs[k][n - n0] * dw[k * CIN + c] * Wpw[(size_t)j * (KK * CIN) + k * CIN + c];
    } else {
        w = Wres[(size_t)(j - COUT) * CIN + c];
    }
    g_wh[idx] = __float2half_rn(w);
}

// ---------------- helpers ----------------
__device__ __forceinline__ void cp_async16(uint32_t dst, const void* src) {
    asm volatile("cp.async.cg.shared.global [%0], [%1], 16;\n" :: "r"(dst), "l"(src));
}
__device__ __forceinline__ void mma16816(float* d, const uint32_t* a, const uint32_t* b) {
    asm volatile(
        "mma.sync.aligned.m16n8k16.row.col.f32.f16.f16.f32 "
        "{%0,%1,%2,%3}, {%4,%5,%6,%7}, {%8,%9}, {%0,%1,%2,%3};\n"
        : "+f"(d[0]), "+f"(d[1]), "+f"(d[2]), "+f"(d[3])
        : "r"(a[0]), "r"(a[1]), "r"(a[2]), "r"(a[3]), "r"(b[0]), "r"(b[1]));
}

// ---------------- K2: fully fused per-(b,n) block ----------------
__global__ void __launch_bounds__(256, 1)
k_fused(const float* __restrict__ x, const float* __restrict__ convw,
        const float* __restrict__ gng, const float* __restrict__ gnb,
        const float* __restrict__ lng, const float* __restrict__ lnb,
        float* __restrict__ out) {
    extern __shared__ char sm[];
    __half* xs   = (__half*)sm;                        // [128][200] halves
    float*  hbuf = (float*)(sm + XS_BYTES);            // [128][264] floats
    __half* bs   = (__half*)(sm + XS_BYTES + HB_BYTES); // 2 x [256][40] halves

    const int n = blockIdx.x, b = blockIdx.y;
    const int tid  = threadIdx.x;
    const int lane = tid & 31, warp = tid >> 5;
    const int g = lane >> 2, q = lane & 3;
    const int wm = warp & 1, wn = warp >> 1;

    const __half* wbase = g_wh + (size_t)n * 512 * CIN;

    // stage one 32-k chunk of B (256 cols) into buffer `buf` via cp.async
    auto stage = [&](int p, int kc, int buf) {
        const __half* src = wbase + (size_t)(p * 256 + tid) * CIN + kc * 32;
        uint32_t d = (uint32_t)__cvta_generic_to_shared(bs + buf * (256 * BS_PITCH) + tid * BS_PITCH);
        cp_async16(d,      src);
        cp_async16(d + 16, src + 8);
        cp_async16(d + 32, src + 16);
        cp_async16(d + 48, src + 24);
        asm volatile("cp.async.commit_group;\n");
    };

    // ---- load x tile -> fp16 smem (overlap with first B stage) ----
    stage(0, 0, 0);
    for (int i = tid; i < 128 * 48; i += 256) {
        int t = i / 48, c4 = (i % 48) * 4;
        float4 v = *(const float4*)(x + ((size_t)(b * Tn + t) * Nn + n) * CIN + c4);
        __half2* dst = (__half2*)(xs + t * XS_PITCH + c4);
        dst[0] = __floats2half2_rn(v.x, v.y);
        dst[1] = __floats2half2_rn(v.z, v.w);
    }
    __syncthreads();

    float acc[4][8][4];

#pragma unroll 1
    for (int p = 0; p < 2; p++) {
#pragma unroll
        for (int mi = 0; mi < 4; mi++)
#pragma unroll
            for (int ni = 0; ni < 8; ni++)
#pragma unroll
                for (int r = 0; r < 4; r++) acc[mi][ni][r] = 0.f;

        if (p == 1) stage(1, 0, 0);

#pragma unroll 1
        for (int kc = 0; kc < 6; kc++) {
            if (kc < 5) {
                stage(p, kc + 1, (kc + 1) & 1);
                asm volatile("cp.async.wait_group 1;\n");
            } else {
                asm volatile("cp.async.wait_group 0;\n");
            }
            __syncthreads();

            const __half* bsc = bs + (kc & 1) * (256 * BS_PITCH);
#pragma unroll
            for (int ks = 0; ks < 2; ks++) {
                const int kb = kc * 32 + ks * 16;
                uint32_t afr[4][4];
                uint32_t bfr[8][2];
#pragma unroll
                for (int mi = 0; mi < 4; mi++) {
                    int t = wm * 64 + mi * 16 + g;
                    afr[mi][0] = *(const uint32_t*)(xs + t       * XS_PITCH + kb + 2 * q);
                    afr[mi][1] = *(const uint32_t*)(xs + (t + 8) * XS_PITCH + kb + 2 * q);
                    afr[mi][2] = *(const uint32_t*)(xs + t       * XS_PITCH + kb + 2 * q + 8);
                    afr[mi][3] = *(const uint32_t*)(xs + (t + 8) * XS_PITCH + kb + 2 * q + 8);
                }
#pragma unroll
                for (int ni = 0; ni < 8; ni++) {
                    int col = wn * 64 + ni * 8 + g;
                    bfr[ni][0] = *(const uint32_t*)(bsc + col * BS_PITCH + ks * 16 + 2 * q);
                    bfr[ni][1] = *(const uint32_t*)(bsc + col * BS_PITCH + ks * 16 + 2 * q + 8);
                }
#pragma unroll
                for (int ni = 0; ni < 8; ni++)
#pragma unroll
                    for (int mi = 0; mi < 4; mi++)
                        mma16816(acc[mi][ni], afr[mi], bfr[ni]);
            }
            __syncthreads();
        }

        if (p == 0) {
            // write h into hbuf[t][o]
#pragma unroll
            for (int mi = 0; mi < 4; mi++) {
                int t0 = wm * 64 + mi * 16 + g;
#pragma unroll
                for (int ni = 0; ni < 8; ni++) {
                    int o0 = wn * 64 + ni * 8 + 2 * q;
                    *(float2*)(hbuf + t0 * HB_PITCH + o0)       = make_float2(acc[mi][ni][0], acc[mi][ni][1]);
                    *(float2*)(hbuf + (t0 + 8) * HB_PITCH + o0) = make_float2(acc[mi][ni][2], acc[mi][ni][3]);
                }
            }
            __syncthreads();

            // ---- temporal depthwise conv + GroupNorm (group == warp) ----
            const int o = tid;
            const float w0 = convw[o * 3], w1 = convw[o * 3 + 1], w2 = convw[o * 3 + 2];
            float prev = 0.f, cur = hbuf[o];
            float s = 0.f, s2 = 0.f;
#pragma unroll 4
            for (int t = 0; t < Tn; t++) {
                float nxt = (t < Tn - 1) ? hbuf[(t + 1) * HB_PITCH + o] : 0.f;
                float v = w0 * prev + w1 * cur + w2 * nxt;
                hbuf[t * HB_PITCH + o] = v;
                s += v; s2 += v * v;
                prev = cur; cur = nxt;
            }
#pragma unroll
            for (int off = 16; off; off >>= 1) {
                s  += __shfl_xor_sync(0xFFFFFFFFu, s,  off);
                s2 += __shfl_xor_sync(0xFFFFFFFFu, s2, off);
            }
            const float inv = 1.f / (32.f * Tn);
            float mu = s * inv;
            float var = s2 * inv - mu * mu;
            float rstd = rsqrtf(var + 1e-5f);
            float ga = gng[o] * rstd;
            float gb = gnb[o] - mu * ga;
#pragma unroll 4
            for (int t = 0; t < Tn; t++)
                hbuf[t * HB_PITCH + o] = hbuf[t * HB_PITCH + o] * ga + gb;
            __syncthreads();
        } else {
            // accumulate residual: hbuf += res
#pragma unroll
            for (int mi = 0; mi < 4; mi++) {
                int t0 = wm * 64 + mi * 16 + g;
#pragma unroll
                for (int ni = 0; ni < 8; ni++) {
                    int o0 = wn * 64 + ni * 8 + 2 * q;
                    float2* p0 = (float2*)(hbuf + t0 * HB_PITCH + o0);
                    float2* p1 = (float2*)(hbuf + (t0 + 8) * HB_PITCH + o0);
                    float2 v0 = *p0, v1 = *p1;
                    v0.x += acc[mi][ni][0]; v0.y += acc[mi][ni][1];
                    v1.x += acc[mi][ni][2]; v1.y += acc[mi][ni][3];
                    *p0 = v0; *p1 = v1;
                }
            }
            __syncthreads();
        }
    }

    // ---- LayerNorm over 256 channels per t + exact GELU + store ----
    float lg[8], lb[8];
#pragma unroll
    for (int j = 0; j < 8; j++) { lg[j] = lng[lane + 32 * j]; lb[j] = lnb[lane + 32 * j]; }

    for (int t = warp; t < Tn; t += 8) {
        float y[8]; float su = 0.f, sq = 0.f;
#pragma unroll
        for (int j = 0; j < 8; j++) {
            float v = hbuf[t * HB_PITCH + lane + 32 * j];
            y[j] = v; su += v; sq += v * v;
        }
#pragma unroll
        for (int off = 16; off; off >>= 1) {
            su += __shfl_xor_sync(0xFFFFFFFFu, su, off);
            sq += __shfl_xor_sync(0xFFFFFFFFu, sq, off);
        }
        float mu = su * (1.f / 256.f);
        float var = sq * (1.f / 256.f) - mu * mu;
        float rs = rsqrtf(var + 1e-5f);
        float* ob = out + ((size_t)(b * Tn + t) * Nn + n) * COUT;
#pragma unroll
        for (int j = 0; j < 8; j++) {
            float v = (y[j] - mu) * rs * lg[j] + lb[j];
            ob[lane + 32 * j] = 0.5f * v * (1.f + erff(v * 0.70710678118654752f));
        }
    }
}

// ---------------- launch ----------------
extern "C" void kernel_launch(void* const* d_in, const int* in_sizes, int n_in,
                              void* d_out, int out_size) {
    const float* x     = (const float*)d_in[0];
    const float* A     = (const float*)d_in[1];
    const float* dw    = (const float*)d_in[2];
    const float* adj   = (const float*)d_in[3];
    const float* Wpw   = (const float*)d_in[4];
    const float* convw = (const float*)d_in[5];
    const float* gng   = (const float*)d_in[6];
    const float* gnb   = (const float*)d_in[7];
    const float* lng   = (const float*)d_in[8];
    const float* lnb   = (const float*)d_in[9];
    const float* Wres  = (const float*)d_in[10];
    float* out = (float*)d_out;

    cudaFuncSetAttribute(k_fused, cudaFuncAttributeMaxDynamicSharedMemorySize, SMEM_TOTAL);

    int total1 = Nn * 512 * CIN;
    k_wh<<<(total1 + 255) / 256, 256>>>(A, adj, dw, Wpw, Wres);
    k_fused<<<dim3(Nn, Bsz), 256, SMEM_TOTAL>>>(x, convw, gng, gnb, lng, lnb, out);
}

// round 8
// speedup vs baseline: 5.3504x; 1.0313x over previous
#include <cuda_runtime.h>
#include <cuda_fp16.h>
#include <cstdint>
#include <math.h>

#define Bsz 32
#define Tn  128
#define Nn  47
#define CIN 192
#define COUT 256
#define KK  3

#define NT   512          // threads per block (16 warps)

#define XS_PITCH 200   // halves per t-row (192 + pad)
#define HB_PITCH 264   // floats per t-row (256 + pad)
#define BS_PITCH 40    // halves per col-row (32 k + pad)

#define XS_BYTES (128 * XS_PITCH * 2)                 // 51200
#define HB_BYTES (128 * HB_PITCH * 4)                 // 135168
#define BS_BYTES (2 * 256 * BS_PITCH * 2)             // 40960
#define SMEM_TOTAL (XS_BYTES + HB_BYTES + BS_BYTES)   // 227328

// ---------------- scratch ----------------
__device__ __align__(256) __half g_wh[(size_t)Nn * 512 * CIN];  // [n][j][c]

// ---------------- K1: rowsum (in-block) + fused fp16 weights [n][j][c] ----------------
__global__ void __launch_bounds__(256) k_wh(const float* __restrict__ A, const float* __restrict__ adj,
                                            const float* __restrict__ dw, const float* __restrict__ Wpw,
                                            const float* __restrict__ Wres) {
    __shared__ float srs[KK][2];
    const int idx0 = blockIdx.x * 256;
    const int n0 = idx0 / (512 * CIN);
    const int warp = threadIdx.x >> 5, lane = threadIdx.x & 31;
    if (warp < 6) {
        int k = warp % KK, nn = n0 + warp / KK;
        if (nn < Nn) {
            const float* ar = A   + ((size_t)k * Nn + nn) * Nn;
            const float* rr = adj + ((size_t)k * Nn + nn) * Nn;
            float s = 0.f, sa = 0.f;
            for (int m = lane; m < Nn; m += 32) {
                float v = ar[m] + 0.3f * tanhf(rr[m]);
                s += v; sa += fabsf(v);
            }
#pragma unroll
            for (int o = 16; o; o >>= 1) {
                s  += __shfl_xor_sync(0xFFFFFFFFu, s,  o);
                sa += __shfl_xor_sync(0xFFFFFFFFu, sa, o);
            }
            if (lane == 0) srs[k][warp / KK] = s / fmaxf(sa, 1.0f);
        }
    }
    __syncthreads();

    const int idx = idx0 + threadIdx.x;
    if (idx >= Nn * 512 * CIN) return;
    int c = idx % CIN;
    int j = (idx / CIN) & 511;
    int n = idx / (CIN * 512);
    float w;
    if (j < COUT) {
        w = 0.f;
#pragma unroll
        for (int k = 0; k < KK; k++)
            w += srs[k][n - n0] * dw[k * CIN + c] * Wpw[(size_t)j * (KK * CIN) + k * CIN + c];
    } else {
        w = Wres[(size_t)(j - COUT) * CIN + c];
    }
    g_wh[idx] = __float2half_rn(w);
}

// ---------------- helpers ----------------
__device__ __forceinline__ void cp_async16(uint32_t dst, const void* src) {
    asm volatile("cp.async.cg.shared.global [%0], [%1], 16;\n" :: "r"(dst), "l"(src));
}
__device__ __forceinline__ void mma16816(float* d, const uint32_t* a, const uint32_t* b) {
    asm volatile(
        "mma.sync.aligned.m16n8k16.row.col.f32.f16.f16.f32 "
        "{%0,%1,%2,%3}, {%4,%5,%6,%7}, {%8,%9}, {%0,%1,%2,%3};\n"
        : "+f"(d[0]), "+f"(d[1]), "+f"(d[2]), "+f"(d[3])
        : "r"(a[0]), "r"(a[1]), "r"(a[2]), "r"(a[3]), "r"(b[0]), "r"(b[1]));
}

// ---------------- K2: fully fused per-(b,n) block, 512 threads ----------------
__global__ void __launch_bounds__(NT, 1)
k_fused(const float* __restrict__ x, const float* __restrict__ convw,
        const float* __restrict__ gng, const float* __restrict__ gnb,
        const float* __restrict__ lng, const float* __restrict__ lnb,
        float* __restrict__ out) {
    extern __shared__ char sm[];
    __half* xs   = (__half*)sm;                         // [128][200] halves
    float*  hbuf = (float*)(sm + XS_BYTES);             // [128][264] floats
    __half* bs   = (__half*)(sm + XS_BYTES + HB_BYTES); // 2 x [256][40] halves
    __shared__ float s_gn[16][2];                       // per-warp GN partials

    const int n = blockIdx.x, b = blockIdx.y;
    const int tid  = threadIdx.x;
    const int lane = tid & 31, warp = tid >> 5;
    const int g = lane >> 2, q = lane & 3;
    const int wm = warp & 1, wn = warp >> 1;            // 2 x 8 warp grid

    const __half* wbase = g_wh + (size_t)n * 512 * CIN;

    // stage one 32-k chunk of B (256 cols) into buffer `buf`; 2 cp.async per thread
    auto stage = [&](int p, int kc, int buf) {
        int col = tid >> 1, hv = tid & 1;
        const __half* src = wbase + (size_t)(p * 256 + col) * CIN + kc * 32 + hv * 16;
        uint32_t d = (uint32_t)__cvta_generic_to_shared(bs + buf * (256 * BS_PITCH) + col * BS_PITCH + hv * 16);
        cp_async16(d,      src);
        cp_async16(d + 16, src + 8);
        asm volatile("cp.async.commit_group;\n");
    };

    // ---- load x tile -> fp16 smem (overlap with first B stage) ----
    stage(0, 0, 0);
    for (int i = tid; i < 128 * 48; i += NT) {
        int t = i / 48, c4 = (i % 48) * 4;
        float4 v = *(const float4*)(x + ((size_t)(b * Tn + t) * Nn + n) * CIN + c4);
        __half2* dst = (__half2*)(xs + t * XS_PITCH + c4);
        dst[0] = __floats2half2_rn(v.x, v.y);
        dst[1] = __floats2half2_rn(v.z, v.w);
    }
    __syncthreads();

    float acc[4][4][4];

#pragma unroll 1
    for (int p = 0; p < 2; p++) {
#pragma unroll
        for (int mi = 0; mi < 4; mi++)
#pragma unroll
            for (int ni = 0; ni < 4; ni++)
#pragma unroll
                for (int r = 0; r < 4; r++) acc[mi][ni][r] = 0.f;

        if (p == 1) stage(1, 0, 0);

#pragma unroll 1
        for (int kc = 0; kc < 6; kc++) {
            if (kc < 5) {
                stage(p, kc + 1, (kc + 1) & 1);
                asm volatile("cp.async.wait_group 1;\n");
            } else {
                asm volatile("cp.async.wait_group 0;\n");
            }
            __syncthreads();

            const __half* bsc = bs + (kc & 1) * (256 * BS_PITCH);
#pragma unroll
            for (int ks = 0; ks < 2; ks++) {
                const int kb = kc * 32 + ks * 16;
                uint32_t afr[4][4];
                uint32_t bfr[4][2];
#pragma unroll
                for (int mi = 0; mi < 4; mi++) {
                    int t = wm * 64 + mi * 16 + g;
                    afr[mi][0] = *(const uint32_t*)(xs + t       * XS_PITCH + kb + 2 * q);
                    afr[mi][1] = *(const uint32_t*)(xs + (t + 8) * XS_PITCH + kb + 2 * q);
                    afr[mi][2] = *(const uint32_t*)(xs + t       * XS_PITCH + kb + 2 * q + 8);
                    afr[mi][3] = *(const uint32_t*)(xs + (t + 8) * XS_PITCH + kb + 2 * q + 8);
                }
#pragma unroll
                for (int ni = 0; ni < 4; ni++) {
                    int col = wn * 32 + ni * 8 + g;
                    bfr[ni][0] = *(const uint32_t*)(bsc + col * BS_PITCH + ks * 16 + 2 * q);
                    bfr[ni][1] = *(const uint32_t*)(bsc + col * BS_PITCH + ks * 16 + 2 * q + 8);
                }
#pragma unroll
                for (int ni = 0; ni < 4; ni++)
#pragma unroll
                    for (int mi = 0; mi < 4; mi++)
                        mma16816(acc[mi][ni], afr[mi], bfr[ni]);
            }
            __syncthreads();
        }

        if (p == 0) {
            // write h into hbuf[t][o]
#pragma unroll
            for (int mi = 0; mi < 4; mi++) {
                int t0 = wm * 64 + mi * 16 + g;
#pragma unroll
                for (int ni = 0; ni < 4; ni++) {
                    int o0 = wn * 32 + ni * 8 + 2 * q;
                    *(float2*)(hbuf + t0 * HB_PITCH + o0)       = make_float2(acc[mi][ni][0], acc[mi][ni][1]);
                    *(float2*)(hbuf + (t0 + 8) * HB_PITCH + o0) = make_float2(acc[mi][ni][2], acc[mi][ni][3]);
                }
            }
            __syncthreads();

            // ---- temporal depthwise conv + GroupNorm; thread = (channel, t-half) ----
            const int o = tid & 255, hf = tid >> 8;
            const int t0 = hf * 64, t1 = t0 + 64;
            const float w0 = convw[o * 3], w1 = convw[o * 3 + 1], w2 = convw[o * 3 + 2];
            // preload boundary values BEFORE anyone writes
            float prev = (t0 == 0) ? 0.f : hbuf[(t0 - 1) * HB_PITCH + o];
            float cur  = hbuf[t0 * HB_PITCH + o];
            float bnd  = (t1 == Tn) ? 0.f : hbuf[t1 * HB_PITCH + o];
            __syncthreads();
            float s = 0.f, s2 = 0.f;
#pragma unroll 4
            for (int t = t0; t < t1; t++) {
                float nxt = (t == t1 - 1) ? bnd : hbuf[(t + 1) * HB_PITCH + o];
                float v = w0 * prev + w1 * cur + w2 * nxt;
                hbuf[t * HB_PITCH + o] = v;
                s += v; s2 += v * v;
                prev = cur; cur = nxt;
            }
#pragma unroll
            for (int off = 16; off; off >>= 1) {
                s  += __shfl_xor_sync(0xFFFFFFFFu, s,  off);
                s2 += __shfl_xor_sync(0xFFFFFFFFu, s2, off);
            }
            if (lane == 0) { s_gn[warp][0] = s; s_gn[warp][1] = s2; }
            __syncthreads();
            const int grp = warp & 7;
            float gs  = s_gn[grp][0] + s_gn[grp + 8][0];
            float gs2 = s_gn[grp][1] + s_gn[grp + 8][1];
            const float inv = 1.f / (32.f * Tn);
            float mu = gs * inv;
            float var = gs2 * inv - mu * mu;
            float rstd = rsqrtf(var + 1e-5f);
            float ga = gng[o] * rstd;
            float gb = gnb[o] - mu * ga;
#pragma unroll 4
            for (int t = t0; t < t1; t++)
                hbuf[t * HB_PITCH + o] = hbuf[t * HB_PITCH + o] * ga + gb;
            __syncthreads();
        } else {
            // accumulate residual: hbuf += res
#pragma unroll
            for (int mi = 0; mi < 4; mi++) {
                int t0 = wm * 64 + mi * 16 + g;
#pragma unroll
                for (int ni = 0; ni < 4; ni++) {
                    int o0 = wn * 32 + ni * 8 + 2 * q;
                    float2* p0 = (float2*)(hbuf + t0 * HB_PITCH + o0);
                    float2* p1 = (float2*)(hbuf + (t0 + 8) * HB_PITCH + o0);
                    float2 v0 = *p0, v1 = *p1;
                    v0.x += acc[mi][ni][0]; v0.y += acc[mi][ni][1];
                    v1.x += acc[mi][ni][2]; v1.y += acc[mi][ni][3];
                    *p0 = v0; *p1 = v1;
                }
            }
            __syncthreads();
        }
    }

    // ---- LayerNorm over 256 channels per t + exact GELU + store (16 warps) ----
    float lg[8], lb[8];
#pragma unroll
    for (int j = 0; j < 8; j++) { lg[j] = lng[lane + 32 * j]; lb[j] = lnb[lane + 32 * j]; }

    for (int t = warp; t < Tn; t += 16) {
        float y[8]; float su = 0.f, sq = 0.f;
#pragma unroll
        for (int j = 0; j < 8; j++) {
            float v = hbuf[t * HB_PITCH + lane + 32 * j];
            y[j] = v; su += v; sq += v * v;
        }
#pragma unroll
        for (int off = 16; off; off >>= 1) {
            su += __shfl_xor_sync(0xFFFFFFFFu, su, off);
            sq += __shfl_xor_sync(0xFFFFFFFFu, sq, off);
        }
        float mu = su * (1.f / 256.f);
        float var = sq * (1.f / 256.f) - mu * mu;
        float rs = rsqrtf(var + 1e-5f);
        float* ob = out + ((size_t)(b * Tn + t) * Nn + n) * COUT;
#pragma unroll
        for (int j = 0; j < 8; j++) {
            float v = (y[j] - mu) * rs * lg[j] + lb[j];
            ob[lane + 32 * j] = 0.5f * v * (1.f + erff(v * 0.70710678118654752f));
        }
    }
}

// ---------------- launch ----------------
extern "C" void kernel_launch(void* const* d_in, const int* in_sizes, int n_in,
                              void* d_out, int out_size) {
    const float* x     = (const float*)d_in[0];
    const float* A     = (const float*)d_in[1];
    const float* dw    = (const float*)d_in[2];
    const float* adj   = (const float*)d_in[3];
    const float* Wpw   = (const float*)d_in[4];
    const float* convw = (const float*)d_in[5];
    const float* gng   = (const float*)d_in[6];
    const float* gnb   = (const float*)d_in[7];
    const float* lng   = (const float*)d_in[8];
    const float* lnb   = (const float*)d_in[9];
    const float* Wres  = (const float*)d_in[10];
    float* out = (float*)d_out;

    cudaFuncSetAttribute(k_fused, cudaFuncAttributeMaxDynamicSharedMemorySize, SMEM_TOTAL);

    int total1 = Nn * 512 * CIN;
    k_wh<<<(total1 + 255) / 256, 256>>>(A, adj, dw, Wpw, Wres);
    k_fused<<<dim3(Nn, Bsz), NT, SMEM_TOTAL>>>(x, convw, gng, gnb, lng, lnb, out);
}

// round 9
// speedup vs baseline: 5.6481x; 1.0556x over previous
#include <cuda_runtime.h>
#include <cuda_fp16.h>
#include <cstdint>
#include <math.h>

#define Bsz 32
#define Tn  128
#define Nn  47
#define CIN 192
#define COUT 256
#define KK  3

#define NT   512          // threads per block (16 warps)

#define XS_PITCH 200   // halves per t-row (192 + pad)
#define HB_PITCH 264   // floats per t-row (256 + pad)
#define BS_PITCH 40    // halves per col-row (32 k + pad)

#define XS_BYTES (128 * XS_PITCH * 2)                 // 51200
#define HB_BYTES (128 * HB_PITCH * 4)                 // 135168
#define BS_HALF  (256 * BS_PITCH * 2)                 // 20480 per buffer
#define BS_BYTES (2 * BS_HALF)                        // 40960
#define SMEM_TOTAL (XS_BYTES + HB_BYTES + BS_BYTES)   // 227328

// ---------------- scratch ----------------
__device__ __align__(256) __half g_wh[(size_t)Nn * 512 * CIN];  // [n][j][c]

// ---------------- K1: rowsum (in-block) + fused fp16 weights [n][j][c] ----------------
__global__ void __launch_bounds__(256) k_wh(const float* __restrict__ A, const float* __restrict__ adj,
                                            const float* __restrict__ dw, const float* __restrict__ Wpw,
                                            const float* __restrict__ Wres) {
    __shared__ float srs[KK][2];
    const int idx0 = blockIdx.x * 256;
    const int n0 = idx0 / (512 * CIN);
    const int warp = threadIdx.x >> 5, lane = threadIdx.x & 31;
    if (warp < 6) {
        int k = warp % KK, nn = n0 + warp / KK;
        if (nn < Nn) {
            const float* ar = A   + ((size_t)k * Nn + nn) * Nn;
            const float* rr = adj + ((size_t)k * Nn + nn) * Nn;
            float s = 0.f, sa = 0.f;
            for (int m = lane; m < Nn; m += 32) {
                float v = ar[m] + 0.3f * tanhf(rr[m]);
                s += v; sa += fabsf(v);
            }
#pragma unroll
            for (int o = 16; o; o >>= 1) {
                s  += __shfl_xor_sync(0xFFFFFFFFu, s,  o);
                sa += __shfl_xor_sync(0xFFFFFFFFu, sa, o);
            }
            if (lane == 0) srs[k][warp / KK] = s / fmaxf(sa, 1.0f);
        }
    }
    __syncthreads();

    const int idx = idx0 + threadIdx.x;
    if (idx >= Nn * 512 * CIN) return;
    int c = idx % CIN;
    int j = (idx / CIN) & 511;
    int n = idx / (CIN * 512);
    float w;
    if (j < COUT) {
        w = 0.f;
#pragma unroll
        for (int k = 0; k < KK; k++)
            w += srs[k][n - n0] * dw[k * CIN + c] * Wpw[(size_t)j * (KK * CIN) + k * CIN + c];
    } else {
        w = Wres[(size_t)(j - COUT) * CIN + c];
    }
    g_wh[idx] = __float2half_rn(w);
}

// ---------------- helpers ----------------
__device__ __forceinline__ void cp_async16(uint32_t dst, const void* src) {
    asm volatile("cp.async.cg.shared.global [%0], [%1], 16;\n" :: "r"(dst), "l"(src));
}
__device__ __forceinline__ void mma16816(float* d, const uint32_t* a, const uint32_t* b) {
    asm volatile(
        "mma.sync.aligned.m16n8k16.row.col.f32.f16.f16.f32 "
        "{%0,%1,%2,%3}, {%4,%5,%6,%7}, {%8,%9}, {%0,%1,%2,%3};\n"
        : "+f"(d[0]), "+f"(d[1]), "+f"(d[2]), "+f"(d[3])
        : "r"(a[0]), "r"(a[1]), "r"(a[2]), "r"(a[3]), "r"(b[0]), "r"(b[1]));
}
__device__ __forceinline__ void ldsm_x4(uint32_t& r0, uint32_t& r1, uint32_t& r2, uint32_t& r3,
                                        uint32_t addr) {
    asm volatile("ldmatrix.sync.aligned.m8n8.x4.shared.b16 {%0,%1,%2,%3}, [%4];"
                 : "=r"(r0), "=r"(r1), "=r"(r2), "=r"(r3) : "r"(addr));
}

// ---------------- K2: fully fused per-(b,n) block, 512 threads, ldmatrix ----------------
__global__ void __launch_bounds__(NT, 1)
k_fused(const float* __restrict__ x, const float* __restrict__ convw,
        const float* __restrict__ gng, const float* __restrict__ gnb,
        const float* __restrict__ lng, const float* __restrict__ lnb,
        float* __restrict__ out) {
    extern __shared__ char sm[];
    __half* xs   = (__half*)sm;                         // [128][200] halves
    float*  hbuf = (float*)(sm + XS_BYTES);             // [128][264] floats
    __half* bs   = (__half*)(sm + XS_BYTES + HB_BYTES); // 2 x [256][40] halves
    __shared__ float s_gn[16][2];
    __shared__ float chA[256], chB[256];                // per-channel GN scale/shift

    const int n = blockIdx.x, b = blockIdx.y;
    const int tid  = threadIdx.x;
    const int lane = tid & 31, warp = tid >> 5;
    const int g = lane >> 2, q = lane & 3;
    const int wm = warp & 1, wn = warp >> 1;            // 2 x 8 warp grid

    const __half* wbase = g_wh + (size_t)n * 512 * CIN;

    const uint32_t xs_u32 = (uint32_t)__cvta_generic_to_shared(xs);
    const uint32_t bs_u32 = (uint32_t)__cvta_generic_to_shared(bs);

    // ldmatrix base addresses (per-lane)
    // A: tile idx = lane>>3: 0:(r0-7,k0-7) 1:(r8-15,k0-7) 2:(r0-7,k8-15) 3:(r8-15,k8-15)
    const int a_row_off = (lane & 7) + ((lane >> 3) & 1) * 8;
    const int a_k_off   = ((lane >> 4) & 1) * 8;
    uint32_t addrA[4];
#pragma unroll
    for (int mi = 0; mi < 4; mi++)
        addrA[mi] = xs_u32 + (uint32_t)((wm * 64 + mi * 16 + a_row_off) * (XS_PITCH * 2) + a_k_off * 2);
    // B: tile idx = lane>>3: 0:(ni even,k0-7) 1:(ni even,k8-15) 2:(ni odd,k0-7) 3:(ni odd,k8-15)
    const int b_n_off = ((lane >> 4) & 1) * 8 + (lane & 7);
    const int b_k_off = ((lane >> 3) & 1) * 8;
    uint32_t addrB[2];
#pragma unroll
    for (int pp = 0; pp < 2; pp++)
        addrB[pp] = bs_u32 + (uint32_t)((wn * 32 + pp * 16 + b_n_off) * (BS_PITCH * 2) + b_k_off * 2);

    // stage one 32-k chunk of B (256 cols) into buffer `buf`; 2 cp.async per thread
    auto stage = [&](int p, int kc, int buf) {
        int col = tid >> 1, hv = tid & 1;
        const __half* src = wbase + (size_t)(p * 256 + col) * CIN + kc * 32 + hv * 16;
        uint32_t d = bs_u32 + (uint32_t)(buf * BS_HALF + col * (BS_PITCH * 2) + hv * 32);
        cp_async16(d,      src);
        cp_async16(d + 16, src + 8);
        asm volatile("cp.async.commit_group;\n");
    };

    // ---- load x tile -> fp16 smem (overlap with first B stage) ----
    stage(0, 0, 0);
    for (int i = tid; i < 128 * 48; i += NT) {
        int t = i / 48, c4 = (i % 48) * 4;
        float4 v = *(const float4*)(x + ((size_t)(b * Tn + t) * Nn + n) * CIN + c4);
        __half2* dst = (__half2*)(xs + t * XS_PITCH + c4);
        dst[0] = __floats2half2_rn(v.x, v.y);
        dst[1] = __floats2half2_rn(v.z, v.w);
    }
    __syncthreads();

    float acc[4][4][4];

#pragma unroll 1
    for (int p = 0; p < 2; p++) {
#pragma unroll
        for (int mi = 0; mi < 4; mi++)
#pragma unroll
            for (int ni = 0; ni < 4; ni++)
#pragma unroll
                for (int r = 0; r < 4; r++) acc[mi][ni][r] = 0.f;

        if (p == 1) stage(1, 0, 0);

#pragma unroll 1
        for (int kc = 0; kc < 6; kc++) {
            if (kc < 5) {
                stage(p, kc + 1, (kc + 1) & 1);
                asm volatile("cp.async.wait_group 1;\n");
            } else {
                asm volatile("cp.async.wait_group 0;\n");
            }
            __syncthreads();

            const uint32_t bsel = (uint32_t)((kc & 1) * BS_HALF);
#pragma unroll
            for (int ks = 0; ks < 2; ks++) {
                const uint32_t kbb = (uint32_t)((kc * 32 + ks * 16) * 2);
                uint32_t afr[4][4];
                uint32_t bfr[4][2];
#pragma unroll
                for (int mi = 0; mi < 4; mi++)
                    ldsm_x4(afr[mi][0], afr[mi][1], afr[mi][2], afr[mi][3], addrA[mi] + kbb);
#pragma unroll
                for (int pp = 0; pp < 2; pp++)
                    ldsm_x4(bfr[pp * 2][0], bfr[pp * 2][1], bfr[pp * 2 + 1][0], bfr[pp * 2 + 1][1],
                            addrB[pp] + bsel + (uint32_t)(ks * 32));
#pragma unroll
                for (int ni = 0; ni < 4; ni++)
#pragma unroll
                    for (int mi = 0; mi < 4; mi++)
                        mma16816(acc[mi][ni], afr[mi], bfr[ni]);
            }
            __syncthreads();
        }

        if (p == 0) {
            // write h into hbuf[t][o]
#pragma unroll
            for (int mi = 0; mi < 4; mi++) {
                int t0 = wm * 64 + mi * 16 + g;
#pragma unroll
                for (int ni = 0; ni < 4; ni++) {
                    int o0 = wn * 32 + ni * 8 + 2 * q;
                    *(float2*)(hbuf + t0 * HB_PITCH + o0)       = make_float2(acc[mi][ni][0], acc[mi][ni][1]);
                    *(float2*)(hbuf + (t0 + 8) * HB_PITCH + o0) = make_float2(acc[mi][ni][2], acc[mi][ni][3]);
                }
            }
            __syncthreads();

            // ---- temporal depthwise conv + GroupNorm stats; thread = (channel, t-half) ----
            const int o = tid & 255, hf = tid >> 8;
            const int t0 = hf * 64, t1 = t0 + 64;
            const float w0 = convw[o * 3], w1 = convw[o * 3 + 1], w2 = convw[o * 3 + 2];
            float prev = (t0 == 0) ? 0.f : hbuf[(t0 - 1) * HB_PITCH + o];
            float cur  = hbuf[t0 * HB_PITCH + o];
            float bnd  = (t1 == Tn) ? 0.f : hbuf[t1 * HB_PITCH + o];
            __syncthreads();
            float s = 0.f, s2 = 0.f;
#pragma unroll 4
            for (int t = t0; t < t1; t++) {
                float nxt = (t == t1 - 1) ? bnd : hbuf[(t + 1) * HB_PITCH + o];
                float v = w0 * prev + w1 * cur + w2 * nxt;
                hbuf[t * HB_PITCH + o] = v;
                s += v; s2 += v * v;
                prev = cur; cur = nxt;
            }
#pragma unroll
            for (int off = 16; off; off >>= 1) {
                s  += __shfl_xor_sync(0xFFFFFFFFu, s,  off);
                s2 += __shfl_xor_sync(0xFFFFFFFFu, s2, off);
            }
            if (lane == 0) { s_gn[warp][0] = s; s_gn[warp][1] = s2; }
            __syncthreads();
            if (hf == 0) {
                const int grp = warp & 7;
                float gs  = s_gn[grp][0] + s_gn[grp + 8][0];
                float gs2 = s_gn[grp][1] + s_gn[grp + 8][1];
                const float inv = 1.f / (32.f * Tn);
                float mu = gs * inv;
                float var = gs2 * inv - mu * mu;
                float rstd = rsqrtf(var + 1e-5f);
                float ga = gng[o] * rstd;
                chA[o] = ga;
                chB[o] = gnb[o] - mu * ga;
            }
            __syncthreads();
        } else {
            // fold GN apply + residual accumulate: hbuf = hbuf*ga + gb + res
#pragma unroll
            for (int ni = 0; ni < 4; ni++) {
                int o0 = wn * 32 + ni * 8 + 2 * q;
                float ca0 = chA[o0], ca1 = chA[o0 + 1];
                float cb0 = chB[o0], cb1 = chB[o0 + 1];
#pragma unroll
                for (int mi = 0; mi < 4; mi++) {
                    int t0 = wm * 64 + mi * 16 + g;
                    float2* p0 = (float2*)(hbuf + t0 * HB_PITCH + o0);
                    float2* p1 = (float2*)(hbuf + (t0 + 8) * HB_PITCH + o0);
                    float2 v0 = *p0, v1 = *p1;
                    v0.x = v0.x * ca0 + cb0 + acc[mi][ni][0];
                    v0.y = v0.y * ca1 + cb1 + acc[mi][ni][1];
                    v1.x = v1.x * ca0 + cb0 + acc[mi][ni][2];
                    v1.y = v1.y * ca1 + cb1 + acc[mi][ni][3];
                    *p0 = v0; *p1 = v1;
                }
            }
            __syncthreads();
        }
    }

    // ---- LayerNorm over 256 channels per t + exact GELU + store (16 warps) ----
    float lg[8], lb[8];
#pragma unroll
    for (int j = 0; j < 8; j++) { lg[j] = lng[lane + 32 * j]; lb[j] = lnb[lane + 32 * j]; }

    for (int t = warp; t < Tn; t += 16) {
        float y[8]; float su = 0.f, sq = 0.f;
#pragma unroll
        for (int j = 0; j < 8; j++) {
            float v = hbuf[t * HB_PITCH + lane + 32 * j];
            y[j] = v; su += v; sq += v * v;
        }
#pragma unroll
        for (int off = 16; off; off >>= 1) {
            su += __shfl_xor_sync(0xFFFFFFFFu, su, off);
            sq += __shfl_xor_sync(0xFFFFFFFFu, sq, off);
        }
        float mu = su * (1.f / 256.f);
        float var = sq * (1.f / 256.f) - mu * mu;
        float rs = rsqrtf(var + 1e-5f);
        float* ob = out + ((size_t)(b * Tn + t) * Nn + n) * COUT;
#pragma unroll
        for (int j = 0; j < 8; j++) {
            float v = (y[j] - mu) * rs * lg[j] + lb[j];
            ob[lane + 32 * j] = 0.5f * v * (1.f + erff(v * 0.70710678118654752f));
        }
    }
}

// ---------------- launch ----------------
extern "C" void kernel_launch(void* const* d_in, const int* in_sizes, int n_in,
                              void* d_out, int out_size) {
    const float* x     = (const float*)d_in[0];
    const float* A     = (const float*)d_in[1];
    const float* dw    = (const float*)d_in[2];
    const float* adj   = (const float*)d_in[3];
    const float* Wpw   = (const float*)d_in[4];
    const float* convw = (const float*)d_in[5];
    const float* gng   = (const float*)d_in[6];
    const float* gnb   = (const float*)d_in[7];
    const float* lng   = (const float*)d_in[8];
    const float* lnb   = (const float*)d_in[9];
    const float* Wres  = (const float*)d_in[10];
    float* out = (float*)d_out;

    cudaFuncSetAttribute(k_fused, cudaFuncAttributeMaxDynamicSharedMemorySize, SMEM_TOTAL);

    int total1 = Nn * 512 * CIN;
    k_wh<<<(total1 + 255) / 256, 256>>>(A, adj, dw, Wpw, Wres);
    k_fused<<<dim3(Nn, Bsz), NT, SMEM_TOTAL>>>(x, convw, gng, gnb, lng, lnb, out);
}

// round 10
// speedup vs baseline: 5.7307x; 1.0146x over previous
#include <cuda_runtime.h>
#include <cuda_fp16.h>
#include <cstdint>
#include <math.h>

#define Bsz 32
#define Tn  128
#define Nn  47
#define CIN 192
#define COUT 256
#define KK  3

#define NT   512          // threads per block (16 warps)

#define XS_PITCH 200   // halves per t-row (192 + pad)
#define HB_PITCH 264   // floats per t-row (256 + pad)
#define BS_PITCH 40    // halves per col-row (32 k + pad)

#define XS_BYTES (128 * XS_PITCH * 2)                 // 51200
#define HB_BYTES (128 * HB_PITCH * 4)                 // 135168
#define BS_HALF  (256 * BS_PITCH * 2)                 // 20480 per buffer
#define BS_BYTES (2 * BS_HALF)                        // 40960
#define SMEM_TOTAL (XS_BYTES + HB_BYTES + BS_BYTES)   // 227328

// ---------------- scratch ----------------
__device__ __align__(256) __half g_wh[(size_t)Nn * 512 * CIN];  // [n][j][c]

// ---------------- K1: rowsum (in-block) + fused fp16 weights, 8-wide ----------------
__global__ void __launch_bounds__(256) k_wh(const float* __restrict__ A, const float* __restrict__ adj,
                                            const float* __restrict__ dw, const float* __restrict__ Wpw,
                                            const float* __restrict__ Wres) {
    __shared__ float srs[KK][2];
    const int idx8_0 = blockIdx.x * 256;
    const int n0 = idx8_0 / (24 * 512);
    const int warp = threadIdx.x >> 5, lane = threadIdx.x & 31;
    if (warp < 6) {
        int k = warp % KK, nn = n0 + warp / KK;
        if (nn < Nn) {
            const float* ar = A   + ((size_t)k * Nn + nn) * Nn;
            const float* rr = adj + ((size_t)k * Nn + nn) * Nn;
            float s = 0.f, sa = 0.f;
            for (int m = lane; m < Nn; m += 32) {
                float v = ar[m] + 0.3f * tanhf(rr[m]);
                s += v; sa += fabsf(v);
            }
#pragma unroll
            for (int o = 16; o; o >>= 1) {
                s  += __shfl_xor_sync(0xFFFFFFFFu, s,  o);
                sa += __shfl_xor_sync(0xFFFFFFFFu, sa, o);
            }
            if (lane == 0) srs[k][warp / KK] = s / fmaxf(sa, 1.0f);
        }
    }
    __syncthreads();

    const int idx8 = idx8_0 + threadIdx.x;
    if (idx8 >= Nn * 512 * 24) return;
    const int c0 = (idx8 % 24) * 8;
    const int j  = (idx8 / 24) & 511;
    const int n  = idx8 / (24 * 512);
    float w8[8];
    if (j < COUT) {
#pragma unroll
        for (int i = 0; i < 8; i++) w8[i] = 0.f;
#pragma unroll
        for (int k = 0; k < KK; k++) {
            float rs = srs[k][n - n0];
            const float* dwp = dw + k * CIN + c0;
            const float* wp  = Wpw + (size_t)j * (KK * CIN) + k * CIN + c0;
            float4 d0 = *(const float4*)dwp, d1 = *(const float4*)(dwp + 4);
            float4 p0 = *(const float4*)wp,  p1 = *(const float4*)(wp + 4);
            w8[0] += rs * d0.x * p0.x; w8[1] += rs * d0.y * p0.y;
            w8[2] += rs * d0.z * p0.z; w8[3] += rs * d0.w * p0.w;
            w8[4] += rs * d1.x * p1.x; w8[5] += rs * d1.y * p1.y;
            w8[6] += rs * d1.z * p1.z; w8[7] += rs * d1.w * p1.w;
        }
    } else {
        const float* rp = Wres + (size_t)(j - COUT) * CIN + c0;
        float4 r0 = *(const float4*)rp, r1 = *(const float4*)(rp + 4);
        w8[0] = r0.x; w8[1] = r0.y; w8[2] = r0.z; w8[3] = r0.w;
        w8[4] = r1.x; w8[5] = r1.y; w8[6] = r1.z; w8[7] = r1.w;
    }
    __half2 h2[4];
#pragma unroll
    for (int i = 0; i < 4; i++) h2[i] = __floats2half2_rn(w8[2 * i], w8[2 * i + 1]);
    *(uint4*)(g_wh + (size_t)idx8 * 8) = *(const uint4*)h2;
}

// ---------------- helpers ----------------
__device__ __forceinline__ void cp_async16(uint32_t dst, const void* src) {
    asm volatile("cp.async.cg.shared.global [%0], [%1], 16;\n" :: "r"(dst), "l"(src));
}
__device__ __forceinline__ void mma16816(float* d, const uint32_t* a, const uint32_t* b) {
    asm volatile(
        "mma.sync.aligned.m16n8k16.row.col.f32.f16.f16.f32 "
        "{%0,%1,%2,%3}, {%4,%5,%6,%7}, {%8,%9}, {%0,%1,%2,%3};\n"
        : "+f"(d[0]), "+f"(d[1]), "+f"(d[2]), "+f"(d[3])
        : "r"(a[0]), "r"(a[1]), "r"(a[2]), "r"(a[3]), "r"(b[0]), "r"(b[1]));
}
__device__ __forceinline__ void ldsm_x4(uint32_t& r0, uint32_t& r1, uint32_t& r2, uint32_t& r3,
                                        uint32_t addr) {
    asm volatile("ldmatrix.sync.aligned.m8n8.x4.shared.b16 {%0,%1,%2,%3}, [%4];"
                 : "=r"(r0), "=r"(r1), "=r"(r2), "=r"(r3) : "r"(addr));
}
__device__ __forceinline__ float gelu_exact(float v) {
    return 0.5f * v * (1.f + erff(v * 0.70710678118654752f));
}

// ---------------- K2: fused per-(b,n) block; conv overlapped into p1 GEMM ----------------
__global__ void __launch_bounds__(NT, 1)
k_fused(const float* __restrict__ x, const float* __restrict__ convw,
        const float* __restrict__ gng, const float* __restrict__ gnb,
        const float* __restrict__ lng, const float* __restrict__ lnb,
        float* __restrict__ out) {
    extern __shared__ char sm[];
    __half* xs   = (__half*)sm;                         // [128][200] halves
    float*  hbuf = (float*)(sm + XS_BYTES);             // [128][264] floats
    __half* bs   = (__half*)(sm + XS_BYTES + HB_BYTES); // 2 x [256][40] halves
    float* part   = (float*)(sm + XS_BYTES + HB_BYTES); // aliases bs buf0 (dead by fold): [128][8][2]
    float* lnstat = part + 2048;                        // [128][2]
    __shared__ float s_gn[16][2];
    __shared__ float chA[256], chB[256];

    const int n = blockIdx.x, b = blockIdx.y;
    const int tid  = threadIdx.x;
    const int lane = tid & 31, warp = tid >> 5;
    const int g = lane >> 2, q = lane & 3;
    const int wm = warp & 1, wn = warp >> 1;            // 2 x 8 warp grid

    const __half* wbase = g_wh + (size_t)n * 512 * CIN;

    const uint32_t xs_u32 = (uint32_t)__cvta_generic_to_shared(xs);
    const uint32_t bs_u32 = (uint32_t)__cvta_generic_to_shared(bs);

    const int a_row_off = (lane & 7) + ((lane >> 3) & 1) * 8;
    const int a_k_off   = ((lane >> 4) & 1) * 8;
    uint32_t addrA[4];
#pragma unroll
    for (int mi = 0; mi < 4; mi++)
        addrA[mi] = xs_u32 + (uint32_t)((wm * 64 + mi * 16 + a_row_off) * (XS_PITCH * 2) + a_k_off * 2);
    const int b_n_off = ((lane >> 4) & 1) * 8 + (lane & 7);
    const int b_k_off = ((lane >> 3) & 1) * 8;
    uint32_t addrB[2];
#pragma unroll
    for (int pp = 0; pp < 2; pp++)
        addrB[pp] = bs_u32 + (uint32_t)((wn * 32 + pp * 16 + b_n_off) * (BS_PITCH * 2) + b_k_off * 2);

    auto stage = [&](int p, int kc, int buf) {
        int col = tid >> 1, hv = tid & 1;
        const __half* src = wbase + (size_t)(p * 256 + col) * CIN + kc * 32 + hv * 16;
        uint32_t d = bs_u32 + (uint32_t)(buf * BS_HALF + col * (BS_PITCH * 2) + hv * 32);
        cp_async16(d,      src);
        cp_async16(d + 16, src + 8);
        asm volatile("cp.async.commit_group;\n");
    };

    // ---- load x tile -> fp16 smem (overlap with first B stage) ----
    stage(0, 0, 0);
    for (int i = tid; i < 128 * 48; i += NT) {
        int t = i / 48, c4 = (i % 48) * 4;
        float4 v = *(const float4*)(x + ((size_t)(b * Tn + t) * Nn + n) * CIN + c4);
        __half2* dst = (__half2*)(xs + t * XS_PITCH + c4);
        dst[0] = __floats2half2_rn(v.x, v.y);
        dst[1] = __floats2half2_rn(v.z, v.w);
    }
    __syncthreads();

    float acc[4][4][4];
#pragma unroll
    for (int mi = 0; mi < 4; mi++)
#pragma unroll
        for (int ni = 0; ni < 4; ni++)
#pragma unroll
            for (int r = 0; r < 4; r++) acc[mi][ni][r] = 0.f;

    // ================= p0 mainloop (h = x @ W_eff) =================
#pragma unroll 1
    for (int kc = 0; kc < 6; kc++) {
        if (kc < 5) {
            stage(0, kc + 1, (kc + 1) & 1);
            asm volatile("cp.async.wait_group 1;\n");
        } else {
            asm volatile("cp.async.wait_group 0;\n");
        }
        __syncthreads();
        const uint32_t bsel = (uint32_t)((kc & 1) * BS_HALF);
#pragma unroll
        for (int ks = 0; ks < 2; ks++) {
            const uint32_t kbb = (uint32_t)((kc * 32 + ks * 16) * 2);
            uint32_t afr[4][4];
            uint32_t bfr[4][2];
#pragma unroll
            for (int mi = 0; mi < 4; mi++)
                ldsm_x4(afr[mi][0], afr[mi][1], afr[mi][2], afr[mi][3], addrA[mi] + kbb);
#pragma unroll
            for (int pp = 0; pp < 2; pp++)
                ldsm_x4(bfr[pp * 2][0], bfr[pp * 2][1], bfr[pp * 2 + 1][0], bfr[pp * 2 + 1][1],
                        addrB[pp] + bsel + (uint32_t)(ks * 32));
#pragma unroll
            for (int ni = 0; ni < 4; ni++)
#pragma unroll
                for (int mi = 0; mi < 4; mi++)
                    mma16816(acc[mi][ni], afr[mi], bfr[ni]);
        }
        __syncthreads();
    }

    // prefetch first p1 chunk while epilogue runs
    stage(1, 0, 0);

    // ---- p0 epilogue: write h into hbuf[t][o] ----
#pragma unroll
    for (int mi = 0; mi < 4; mi++) {
        int t0e = wm * 64 + mi * 16 + g;
#pragma unroll
        for (int ni = 0; ni < 4; ni++) {
            int o0 = wn * 32 + ni * 8 + 2 * q;
            *(float2*)(hbuf + t0e * HB_PITCH + o0)       = make_float2(acc[mi][ni][0], acc[mi][ni][1]);
            *(float2*)(hbuf + (t0e + 8) * HB_PITCH + o0) = make_float2(acc[mi][ni][2], acc[mi][ni][3]);
        }
    }
    __syncthreads();

    // ---- conv setup: thread = (channel, t-half); preload boundaries ----
    const int o = tid & 255, hf = tid >> 8;
    const int ct0 = hf * 64, ct1 = ct0 + 64;
    const float w0 = convw[o * 3], w1 = convw[o * 3 + 1], w2 = convw[o * 3 + 2];
    float cprev = (ct0 == 0) ? 0.f : hbuf[(ct0 - 1) * HB_PITCH + o];
    float ccur  = hbuf[ct0 * HB_PITCH + o];
    float cbnd  = (ct1 == Tn) ? 0.f : hbuf[ct1 * HB_PITCH + o];
    float cs = 0.f, cs2 = 0.f;
    int tc = ct0;

    // zero acc for p1
#pragma unroll
    for (int mi = 0; mi < 4; mi++)
#pragma unroll
        for (int ni = 0; ni < 4; ni++)
#pragma unroll
            for (int r = 0; r < 4; r++) acc[mi][ni][r] = 0.f;

    // ================= p1 mainloop (res = x @ W_res) + conv interleave =================
#pragma unroll 1
    for (int kc = 0; kc < 6; kc++) {
        if (kc < 5) {
            stage(1, kc + 1, (kc + 1) & 1);
            asm volatile("cp.async.wait_group 1;\n");
        } else {
            asm volatile("cp.async.wait_group 0;\n");
        }
        __syncthreads();
        const uint32_t bsel = (uint32_t)((kc & 1) * BS_HALF);
#pragma unroll
        for (int ks = 0; ks < 2; ks++) {
            const uint32_t kbb = (uint32_t)((kc * 32 + ks * 16) * 2);
            uint32_t afr[4][4];
            uint32_t bfr[4][2];
#pragma unroll
            for (int mi = 0; mi < 4; mi++)
                ldsm_x4(afr[mi][0], afr[mi][1], afr[mi][2], afr[mi][3], addrA[mi] + kbb);
#pragma unroll
            for (int pp = 0; pp < 2; pp++)
                ldsm_x4(bfr[pp * 2][0], bfr[pp * 2][1], bfr[pp * 2 + 1][0], bfr[pp * 2 + 1][1],
                        addrB[pp] + bsel + (uint32_t)(ks * 32));
#pragma unroll
            for (int ni = 0; ni < 4; ni++)
#pragma unroll
                for (int mi = 0; mi < 4; mi++)
                    mma16816(acc[mi][ni], afr[mi], bfr[ni]);
        }
        // ---- conv slice (fills mma shadow; touches only hbuf) ----
        {
            int te = tc + 11; if (te > ct1) te = ct1;
            for (int t = tc; t < te; t++) {
                float nxt = (t == ct1 - 1) ? cbnd : hbuf[(t + 1) * HB_PITCH + o];
                float v = w0 * cprev + w1 * ccur + w2 * nxt;
                hbuf[t * HB_PITCH + o] = v;
                cs += v; cs2 += v * v;
                cprev = ccur; ccur = nxt;
            }
            tc = te;
        }
        __syncthreads();
    }

    // ---- GN stats finalize ----
#pragma unroll
    for (int off = 16; off; off >>= 1) {
        cs  += __shfl_xor_sync(0xFFFFFFFFu, cs,  off);
        cs2 += __shfl_xor_sync(0xFFFFFFFFu, cs2, off);
    }
    if (lane == 0) { s_gn[warp][0] = cs; s_gn[warp][1] = cs2; }
    __syncthreads();
    if (hf == 0) {
        const int grp = warp & 7;
        float gs  = s_gn[grp][0] + s_gn[grp + 8][0];
        float gs2 = s_gn[grp][1] + s_gn[grp + 8][1];
        const float inv = 1.f / (32.f * Tn);
        float mu = gs * inv;
        float var = gs2 * inv - mu * mu;
        float rstd = rsqrtf(var + 1e-5f);
        float ga = gng[o] * rstd;
        chA[o] = ga;
        chB[o] = gnb[o] - mu * ga;
    }
    __syncthreads();

    // ---- fold: v = h*ga + gb + res (in regs) + LN partial sums ----
#pragma unroll
    for (int mi = 0; mi < 4; mi++) {
#pragma unroll
        for (int half = 0; half < 2; half++) {
            int t = wm * 64 + mi * 16 + g + half * 8;
            float su = 0.f, sq = 0.f;
#pragma unroll
            for (int ni = 0; ni < 4; ni++) {
                int o0 = wn * 32 + ni * 8 + 2 * q;
                float2 hv = *(const float2*)(hbuf + t * HB_PITCH + o0);
                int r = half * 2;
                float v0 = hv.x * chA[o0]     + chB[o0]     + acc[mi][ni][r];
                float v1 = hv.y * chA[o0 + 1] + chB[o0 + 1] + acc[mi][ni][r + 1];
                acc[mi][ni][r] = v0; acc[mi][ni][r + 1] = v1;
                su += v0 + v1; sq += v0 * v0 + v1 * v1;
            }
            su += __shfl_xor_sync(0xFFFFFFFFu, su, 1);
            su += __shfl_xor_sync(0xFFFFFFFFu, su, 2);
            sq += __shfl_xor_sync(0xFFFFFFFFu, sq, 1);
            sq += __shfl_xor_sync(0xFFFFFFFFu, sq, 2);
            if (q == 0) *(float2*)(part + (t * 8 + wn) * 2) = make_float2(su, sq);
        }
    }
    __syncthreads();
    if (tid < Tn) {
        float su = 0.f, sq = 0.f;
#pragma unroll
        for (int w = 0; w < 8; w++) {
            float2 p = *(const float2*)(part + (tid * 8 + w) * 2);
            su += p.x; sq += p.y;
        }
        float mu = su * (1.f / 256.f);
        float var = sq * (1.f / 256.f) - mu * mu;
        *(float2*)(lnstat + tid * 2) = make_float2(mu, rsqrtf(var + 1e-5f));
    }
    __syncthreads();

    // ---- apply LN + GELU from regs, direct store ----
#pragma unroll
    for (int mi = 0; mi < 4; mi++) {
#pragma unroll
        for (int half = 0; half < 2; half++) {
            int t = wm * 64 + mi * 16 + g + half * 8;
            float2 st = *(const float2*)(lnstat + t * 2);
            float mu = st.x, rs = st.y;
            float* ob = out + ((size_t)(b * Tn + t) * Nn + n) * COUT;
            int r = half * 2;
#pragma unroll
            for (int ni = 0; ni < 4; ni++) {
                int o0 = wn * 32 + ni * 8 + 2 * q;
                float2 lg = *(const float2*)(lng + o0);
                float2 lb = *(const float2*)(lnb + o0);
                float y0 = (acc[mi][ni][r]     - mu) * rs * lg.x + lb.x;
                float y1 = (acc[mi][ni][r + 1] - mu) * rs * lg.y + lb.y;
                *(float2*)(ob + o0) = make_float2(gelu_exact(y0), gelu_exact(y1));
            }
        }
    }
}

// ---------------- launch ----------------
extern "C" void kernel_launch(void* const* d_in, const int* in_sizes, int n_in,
                              void* d_out, int out_size) {
    const float* x     = (const float*)d_in[0];
    const float* A     = (const float*)d_in[1];
    const float* dw    = (const float*)d_in[2];
    const float* adj   = (const float*)d_in[3];
    const float* Wpw   = (const float*)d_in[4];
    const float* convw = (const float*)d_in[5];
    const float* gng   = (const float*)d_in[6];
    const float* gnb   = (const float*)d_in[7];
    const float* lng   = (const float*)d_in[8];
    const float* lnb   = (const float*)d_in[9];
    const float* Wres  = (const float*)d_in[10];
    float* out = (float*)d_out;

    cudaFuncSetAttribute(k_fused, cudaFuncAttributeMaxDynamicSharedMemorySize, SMEM_TOTAL);

    int total8 = Nn * 512 * 24;
    k_wh<<<(total8 + 255) / 256, 256>>>(A, adj, dw, Wpw, Wres);
    k_fused<<<dim3(Nn, Bsz), NT, SMEM_TOTAL>>>(x, convw, gng, gnb, lng, lnb, out);
}